// round 15
// baseline (speedup 1.0000x reference)
#include <cuda_runtime.h>
#include <math.h>
#include <string.h>

#ifndef M_PI
#define M_PI 3.14159265358979323846
#endif

// WINNING sign config (R12): flip p10 only.
#ifndef SIGN_FLIP_MASK
#define SIGN_FLIP_MASK (1u << 10)
#endif

#define NLUT 1024
#define RMAX 8.0f
#define LUT_FLOATS (NLUT * 13)                    // 13312
#define STAGE_FLOATS 4608                         // 512 edges * 9
#define SMEM_FLOATS (LUT_FLOATS + 160 + STAGE_FLOATS)
#define SMEM_BYTES (SMEM_FLOATS * 4)              // 72320 B
#define NBLOCKS 296
#define NTHREADS 256
#define TILE 512                                  // edges per block-iteration

// ---------------------------------------------------------------------------
// Path metadata (l1,l2,l3) in reference order
// ---------------------------------------------------------------------------
static const int H_O1[13] = {0,0,0,1,1,1,1,4,4,4,4,9,9};
static const int H_D1[13] = {1,1,1,3,3,3,3,5,5,5,5,7,7};
static const int H_O2[13] = {0,1,4,0,1,1,4,0,1,4,4,1,4};
static const int H_D2[13] = {1,3,5,1,3,3,5,1,3,5,5,3,5};
static const int H_O3[13] = {0,1,4,1,0,4,1,4,1,0,4,4,1};
static const int H_D3[13] = {1,3,5,3,1,5,3,5,3,1,5,5,3};
static const int H_COFF[13] = {0,1,10,35,44,53,98,143,168,213,238,363,468};

__constant__ int c_O1[13] = {0,0,0,1,1,1,1,4,4,4,4,9,9};
__constant__ int c_D1[13] = {1,1,1,3,3,3,3,5,5,5,5,7,7};
__constant__ int c_D2[13] = {1,3,5,1,3,3,5,1,3,5,5,3,5};
__constant__ int c_D3[13] = {1,3,5,3,1,5,3,5,3,1,5,5,3};
__constant__ int c_COFF[13] = {0,1,10,35,44,53,98,143,168,213,238,363,468};
__constant__ int c_MOFF[13] = {0,1,10,35,38,41,56,71,76,85,90,115,130};

struct CoefPack { float c[573]; };

__device__ float g_M[160];
__device__ float g_LUT[LUT_FLOATS];

// ---------------------------------------------------------------------------
static void sph_all(double x, double y, double z, double* Y) {
    const double s3 = sqrt(3.0), s15 = sqrt(15.0), s5 = sqrt(5.0);
    const double s70 = sqrt(70.0), s105 = sqrt(105.0), s42 = sqrt(42.0), s7 = sqrt(7.0);
    Y[0] = 1.0;
    Y[1] = s3 * x; Y[2] = s3 * y; Y[3] = s3 * z;
    Y[4] = s15 * x * z;
    Y[5] = s15 * x * y;
    Y[6] = s5 * (y * y - 0.5 * (x * x + z * z));
    Y[7] = s15 * y * z;
    Y[8] = 0.5 * s15 * (z * z - x * x);
    Y[9]  = 0.25 * s70 * x * (3.0 * z * z - x * x);
    Y[10] = s105 * x * y * z;
    Y[11] = 0.25 * s42 * x * (5.0 * y * y - 1.0);
    Y[12] = 0.5 * s7 * (5.0 * y * y * y - 3.0 * y);
    Y[13] = 0.25 * s42 * z * (5.0 * y * y - 1.0);
    Y[14] = 0.5 * s105 * y * (z * z - x * x);
    Y[15] = 0.25 * s70 * z * (z * z - 3.0 * x * x);
}

static void gl_nodes(int n, double* x, double* w) {
    for (int i = 0; i < n; i++) {
        double xi = cos(M_PI * (i + 0.75) / (n + 0.5));
        double p0 = 1.0, p1 = 0.0;
        for (int it = 0; it < 100; it++) {
            p0 = 1.0; p1 = 0.0;
            for (int j = 0; j < n; j++) {
                double p2 = p1; p1 = p0;
                p0 = ((2.0 * j + 1.0) * xi * p1 - j * p2) / (j + 1.0);
            }
            double dp = n * (xi * p0 - p1) / (xi * xi - 1.0);
            double dx = p0 / dp;
            xi -= dx;
            if (fabs(dx) < 1e-15) break;
        }
        p0 = 1.0; p1 = 0.0;
        for (int j = 0; j < n; j++) {
            double p2 = p1; p1 = p0;
            p0 = ((2.0 * j + 1.0) * xi * p1 - j * p2) / (j + 1.0);
        }
        double dp = n * (xi * p0 - p1) / (xi * xi - 1.0);
        x[i] = xi;
        w[i] = 2.0 / ((1.0 - xi * xi) * dp * dp);
    }
}

static void build_coefs(CoefPack& cp) {
    const int NG = 20, NP = 24;
    double xn[NG], wn[NG];
    gl_nodes(NG, xn, wn);

    static double g[573];
    memset(g, 0, sizeof(g));

    for (int iz = 0; iz < NG; iz++) {
        double ct = xn[iz];
        double st2 = 1.0 - ct * ct;
        double st = st2 > 0.0 ? sqrt(st2) : 0.0;
        for (int ip = 0; ip < NP; ip++) {
            double phi = 2.0 * M_PI * ip / NP;
            double vx = st * cos(phi), vy = st * sin(phi), vz = ct;
            double Y[16];
            sph_all(vx, vy, vz, Y);
            double wq = wn[iz];
            for (int p = 0; p < 13; p++) {
                int idx = H_COFF[p];
                const int o1 = H_O1[p], d1 = H_D1[p];
                const int o2 = H_O2[p], d2 = H_D2[p];
                const int o3 = H_O3[p], d3 = H_D3[p];
                for (int i = 0; i < d1; i++) {
                    double yi = wq * Y[o1 + i];
                    for (int j = 0; j < d2; j++) {
                        double yij = yi * Y[o2 + j];
                        for (int k = 0; k < d3; k++)
                            g[idx++] += yij * Y[o3 + k];
                    }
                }
            }
        }
    }

    const double a13 = sqrt(1.0 / 3.0), a35 = sqrt(3.0 / 5.0);
    const double alpha[13] = {a13, a35, 1.0, a35, a13, 1.0, a35, 1.0, a35, a13, 1.0, 1.0, a35};

    for (int p = 0; p < 13; p++) {
        int n = H_D1[p] * H_D2[p] * H_D3[p];
        int off = H_COFF[p];
        double nrm = 0.0;
        for (int i = 0; i < n; i++) nrm += g[off + i] * g[off + i];
        nrm = sqrt(nrm);
        double mx = 0.0;
        for (int i = 0; i < n; i++) { double a = fabs(g[off + i]); if (a > mx) mx = a; }
        int first = 0;
        for (int i = 0; i < n; i++) { if (fabs(g[off + i]) >= mx * (1.0 - 1e-9)) { first = i; break; } }
        double sgn = (g[off + first] < 0.0) ? -1.0 : 1.0;
        if ((SIGN_FLIP_MASK >> p) & 1u) sgn = -sgn;
        double scale = sgn * alpha[p] / nrm;
        for (int i = 0; i < n; i++) cp.c[off + i] = (float)(g[off + i] * scale);
    }
}

static double silu_const_host() {
    const int n = 48001;
    const double a = -12.0, b = 12.0;
    const double h = (b - a) / (n - 1);
    const double inv_s2pi = 1.0 / sqrt(2.0 * M_PI);
    double s = 0.0;
    for (int i = 0; i < n; i++) {
        double z = a + i * h;
        double sig = 1.0 / (1.0 + exp(-z));
        double f = z * sig;
        f = f * f * exp(-0.5 * z * z) * inv_s2pi;
        s += (i == 0 || i == n - 1) ? 0.5 * f : f;
    }
    s *= h;
    return 1.0 / sqrt(s);
}

// ---------------------------------------------------------------------------
// Setup kernel: blocks 0-3 build the radial LUT, block 4 builds M.
// ---------------------------------------------------------------------------
__global__ void setup_kernel(const float* __restrict__ f_in,
                             const float* __restrict__ w1,
                             const float* __restrict__ w2,
                             CoefPack cp, float hscale) {
    int t = threadIdx.x;
    if (blockIdx.x < 4) {
        int i = blockIdx.x * 256 + t;
        if (i >= NLUT) return;
        float r = (float)i * (RMAX / (float)(NLUT - 1));
        float emb[8];
#pragma unroll
        for (int b = 0; b < 8; b++) {
            float d = (r - 0.6666666666666666f * (b + 1)) * 1.5f;
            emb[b] = expf(-d * d);
        }
        float wv[13];
#pragma unroll
        for (int p = 0; p < 13; p++) wv[p] = 0.f;
        for (int c = 0; c < 32; c++) {
            float a = 0.f;
#pragma unroll
            for (int b = 0; b < 8; b++)
                a += emb[b] * (w1[b * 32 + c] * 0.8928571428571429f);  // 1/1.12
            float hg = a / (1.0f + expf(-a));                          // silu
#pragma unroll
            for (int p = 0; p < 13; p++) wv[p] += hg * w2[c * 13 + p];
        }
#pragma unroll
        for (int p = 0; p < 13; p++) g_LUT[i * 13 + p] = wv[p];
    } else {
        __shared__ float src[16];
        if (t < 16) src[t] = f_in[t];
        __syncthreads();
        if (t >= 145) return;
        int p = 0;
        while (p < 12 && t >= c_MOFF[p + 1]) p++;
        int local = t - c_MOFF[p];
        int d1 = c_D1[p], d2 = c_D2[p], d3 = c_D3[p];
        int j = local / d3, k = local % d3;
        float acc = 0.f;
        for (int i = 0; i < d1; i++)
            acc += cp.c[c_COFF[p] + (i * d2 + j) * d3 + k] * src[c_O1[p] + i];
        g_M[t] = acc * hscale;
    }
}

// ---------------------------------------------------------------------------
// Dual-edge contraction helper: one Ms load feeds both edges' FMAs.
// ---------------------------------------------------------------------------
template <int D2, int D3>
__device__ __forceinline__ void contract2(const float* __restrict__ Ms, int base,
                                          const float* q0, const float* q1,
                                          float* o0, float* o1, int obase) {
#pragma unroll
    for (int j = 0; j < D2; j++) {
#pragma unroll
        for (int k = 0; k < D3; k++) {
            float m = Ms[base + j * D3 + k];
            o0[obase + k] = fmaf(m, q0[j], o0[obase + k]);
            o1[obase + k] = fmaf(m, q1[j], o1[obase + k]);
        }
    }
}

// ---------------------------------------------------------------------------
// Main kernel: persistent blocks, TWO edges per thread per tile (512/block).
// Smem: [0,13312) LUT | [13312,13472) Ms | [13472,18080) stage (4608 floats)
// ---------------------------------------------------------------------------
__global__ __launch_bounds__(NTHREADS) void conv_kernel(
    const float* __restrict__ pos,
    float* __restrict__ out, int N)
{
    extern __shared__ float sm[];
    float* lut_s = sm;
    const float* __restrict__ Ms = sm + LUT_FLOATS;
    float* stage = sm + LUT_FLOATS + 160;

    const int t = threadIdx.x;
    for (int i = t; i < LUT_FLOATS; i += NTHREADS) lut_s[i] = g_LUT[i];
    if (t < 145) ((float*)Ms)[t] = g_M[t];

    const int ntiles = (N + TILE - 1) / TILE;
    const long long total3 = (long long)N * 3;
    const long long total9 = (long long)N * 9;
    const float uscale = (float)(NLUT - 1) / RMAX;

    const float S3 = 1.7320508075688772f;
    const float S15 = 3.872983346207417f;
    const float S5 = 2.23606797749979f;
    const float S15H = 1.9364916731037085f;

    for (int tile = blockIdx.x; tile < ntiles; tile += gridDim.x) {
        long long base3 = (long long)tile * (TILE * 3);

        __syncthreads();   // LUT/Ms ready (iter 0); stage free of previous readers
#pragma unroll
        for (int i = 0; i < 6; i++) {
            int si = i * NTHREADS + t;
            long long gi = base3 + si;
            stage[si] = (gi < total3) ? pos[gi] : 0.f;
        }
        __syncthreads();

        // ---- per-edge setup (A = t, B = t+256) ----
        float sA[8], sB[8], wvA[13], wvB[13];
        {
            float x = stage[3 * t], y = stage[3 * t + 1], z = stage[3 * t + 2];
            float r = sqrtf(x * x + y * y + z * z);
            float inv = (r > 0.f) ? (1.0f / r) : 1.0f;
            float ux = x * inv, uy = y * inv, uz = z * inv;
            sA[0] = S3 * ux; sA[1] = S3 * uy; sA[2] = S3 * uz;
            sA[3] = S15 * ux * uz; sA[4] = S15 * ux * uy;
            sA[5] = S5 * (uy * uy - 0.5f * (ux * ux + uz * uz));
            sA[6] = S15 * uy * uz; sA[7] = S15H * (uz * uz - ux * ux);
            float u = r * uscale;
            int idx = (int)u;
            if (idx > NLUT - 2) idx = NLUT - 2;
            float f = u - (float)idx;
            const float* lp = lut_s + idx * 13;
#pragma unroll
            for (int p = 0; p < 13; p++) {
                float a = lp[p], b = lp[p + 13];
                wvA[p] = fmaf(f, b - a, a);
            }
        }
        {
            float x = stage[768 + 3 * t], y = stage[768 + 3 * t + 1], z = stage[768 + 3 * t + 2];
            float r = sqrtf(x * x + y * y + z * z);
            float inv = (r > 0.f) ? (1.0f / r) : 1.0f;
            float ux = x * inv, uy = y * inv, uz = z * inv;
            sB[0] = S3 * ux; sB[1] = S3 * uy; sB[2] = S3 * uz;
            sB[3] = S15 * ux * uz; sB[4] = S15 * ux * uy;
            sB[5] = S5 * (uy * uy - 0.5f * (ux * ux + uz * uz));
            sB[6] = S15 * uy * uz; sB[7] = S15H * (uz * uz - ux * ux);
            float u = r * uscale;
            int idx = (int)u;
            if (idx > NLUT - 2) idx = NLUT - 2;
            float f = u - (float)idx;
            const float* lp = lut_s + idx * 13;
#pragma unroll
            for (int p = 0; p < 13; p++) {
                float a = lp[p], b = lp[p + 13];
                wvB[p] = fmaf(f, b - a, a);
            }
        }

        float oA[9], oB[9];
#pragma unroll
        for (int k = 0; k < 9; k++) { oA[k] = 0.f; oB[k] = 0.f; }

        float qA[5], qB[5];
        // p0 (0,0,0): q = wv0
        contract2<1, 1>(Ms, 0, &wvA[0], &wvB[0], oA, oB, 0);
        // p1 (0,1,1): q = wv1 * s123
#pragma unroll
        for (int j = 0; j < 3; j++) { qA[j] = wvA[1] * sA[j]; qB[j] = wvB[1] * sB[j]; }
        contract2<3, 3>(Ms, 1, qA, qB, oA, oB, 1);
        // p2 (0,2,2): q = wv2 * s45678
#pragma unroll
        for (int j = 0; j < 5; j++) { qA[j] = wvA[2] * sA[3 + j]; qB[j] = wvB[2] * sB[3 + j]; }
        contract2<5, 5>(Ms, 10, qA, qB, oA, oB, 4);
        // p3 (1,0,1): q = wv3
        contract2<1, 3>(Ms, 35, &wvA[3], &wvB[3], oA, oB, 1);
        // p4 (1,1,0): q = wv4 * s123
#pragma unroll
        for (int j = 0; j < 3; j++) { qA[j] = wvA[4] * sA[j]; qB[j] = wvB[4] * sB[j]; }
        contract2<3, 1>(Ms, 38, qA, qB, oA, oB, 0);
        // p5 (1,1,2): q = wv5 * s123
#pragma unroll
        for (int j = 0; j < 3; j++) { qA[j] = wvA[5] * sA[j]; qB[j] = wvB[5] * sB[j]; }
        contract2<3, 5>(Ms, 41, qA, qB, oA, oB, 4);
        // p6 (1,2,1): q = wv6 * s45678
#pragma unroll
        for (int j = 0; j < 5; j++) { qA[j] = wvA[6] * sA[3 + j]; qB[j] = wvB[6] * sB[3 + j]; }
        contract2<5, 3>(Ms, 56, qA, qB, oA, oB, 1);
        // p7 (2,0,2): q = wv7
        contract2<1, 5>(Ms, 71, &wvA[7], &wvB[7], oA, oB, 4);
        // p8 (2,1,1): q = wv8 * s123
#pragma unroll
        for (int j = 0; j < 3; j++) { qA[j] = wvA[8] * sA[j]; qB[j] = wvB[8] * sB[j]; }
        contract2<3, 3>(Ms, 76, qA, qB, oA, oB, 1);
        // p9 (2,2,0): q = wv9 * s45678
#pragma unroll
        for (int j = 0; j < 5; j++) { qA[j] = wvA[9] * sA[3 + j]; qB[j] = wvB[9] * sB[3 + j]; }
        contract2<5, 1>(Ms, 85, qA, qB, oA, oB, 0);
        // p10 (2,2,2): q = wv10 * s45678
#pragma unroll
        for (int j = 0; j < 5; j++) { qA[j] = wvA[10] * sA[3 + j]; qB[j] = wvB[10] * sB[3 + j]; }
        contract2<5, 5>(Ms, 90, qA, qB, oA, oB, 4);
        // p11 (3,1,2): q = wv11 * s123
#pragma unroll
        for (int j = 0; j < 3; j++) { qA[j] = wvA[11] * sA[j]; qB[j] = wvB[11] * sB[j]; }
        contract2<3, 5>(Ms, 115, qA, qB, oA, oB, 4);
        // p12 (3,2,1): q = wv12 * s45678
#pragma unroll
        for (int j = 0; j < 5; j++) { qA[j] = wvA[12] * sA[3 + j]; qB[j] = wvB[12] * sB[3 + j]; }
        contract2<5, 3>(Ms, 130, qA, qB, oA, oB, 1);

        // ---- stage + coalesced store ----
        __syncthreads();   // pos reads done before stage reuse
#pragma unroll
        for (int k = 0; k < 9; k++) {
            stage[t * 9 + k] = oA[k];
            stage[2304 + t * 9 + k] = oB[k];
        }
        __syncthreads();

        long long base9 = (long long)tile * (TILE * 9);
#pragma unroll
        for (int i = 0; i < 18; i++) {
            int si = i * NTHREADS + t;
            long long gi = base9 + si;
            if (gi < total9) out[gi] = stage[si];
        }
    }
}

// ---------------------------------------------------------------------------
extern "C" void kernel_launch(void* const* d_in, const int* in_sizes, int n_in,
                              void* d_out, int out_size)
{
    const float* f_in = (const float*)d_in[0];
    const float* pos  = (const float*)d_in[1];
    const float* w1   = (const float*)d_in[2];
    const float* w2   = (const float*)d_in[3];
    (void)n_in; (void)out_size;
    const int N = in_sizes[1] / 3;

    CoefPack cp;
    build_coefs(cp);
    float hscale = (float)(silu_const_host() / sqrt(32.0));

    cudaFuncSetAttribute(conv_kernel, cudaFuncAttributeMaxDynamicSharedMemorySize, SMEM_BYTES);

    setup_kernel<<<5, 256>>>(f_in, w1, w2, cp, hscale);
    conv_kernel<<<NBLOCKS, NTHREADS, SMEM_BYTES>>>(pos, (float*)d_out, N);
}